// round 6
// baseline (speedup 1.0000x reference)
#include <cuda_runtime.h>

#define N_ATOMS 1024
#define NPAIRS  512          // packed column-pairs per copy
#define TPB     256
#define NSEG    8            // k-segments; 256 packed k-steps total
#define PSTEPS  32           // packed k-steps per CTA

__device__ float g_partials[1024];
__device__ unsigned int g_count = 0;

typedef unsigned long long u64;

__device__ __forceinline__ u64 fma2(u64 a, u64 b, u64 c) {
    u64 d; asm("fma.rn.f32x2 %0, %1, %2, %3;" : "=l"(d) : "l"(a), "l"(b), "l"(c)); return d;
}
__device__ __forceinline__ u64 add2(u64 a, u64 b) {
    u64 d; asm("add.rn.f32x2 %0, %1, %2;" : "=l"(d) : "l"(a), "l"(b)); return d;
}
__device__ __forceinline__ u64 pack2(float lo, float hi) {
    u64 d; asm("mov.b64 %0, {%1, %2};" : "=l"(d) : "f"(lo), "f"(hi)); return d;
}
__device__ __forceinline__ float fsqrt_approx(float x) {
    float r; asm("sqrt.approx.f32 %0, %1;" : "=f"(r) : "f"(x)); return r;
}

// padded packed-slot index in float4 units: slot c -> 2c + c/4 (16B pad per 4 slots)
#define PSLOT(c) (2 * (c) + ((c) >> 2))

// one packed op = 2 pairs
#define PAIR2(X, Y, Z, R, sx, sy, sz, sr, ACC) do {                          \
    u64 _t = fma2(X, sx, fma2(Y, sy, fma2(Z, sz, sr)));                      \
    u64 _d2 = add2(_t, R);                                                   \
    float _a, _b;                                                            \
    asm("mov.b64 {%0, %1}, %2;" : "=f"(_a), "=f"(_b) : "l"(_d2));            \
    float _v0 = fmaxf(2.9f - fsqrt_approx(_a), 0.0f);                        \
    float _v1 = fmaxf(2.9f - fsqrt_approx(_b), 0.0f);                        \
    ACC = fmaf(_v0, _v0, ACC);                                               \
    ACC = fmaf(_v1, _v1, ACC);                                               \
} while (0)

#define LOAD_SLOT(s, cidx) do {                                              \
    int _f4 = PSLOT(cidx);                                                   \
    const ulonglong2* _p = reinterpret_cast<const ulonglong2*>(cp + _f4);    \
    ulonglong2 _u = _p[0];                                                   \
    ulonglong2 _w = _p[1];                                                   \
    s##x = _u.x; s##y = _u.y; s##z = _w.x; s##r = _w.y;                      \
} while (0)

// one k-step: 2 rows x 2 packed pairs; refill slot a (used again 2 steps later)
#define STEP2(a, b) do {                                                     \
    PAIR2(X0, Y0, Z0, R0, a##x, a##y, a##z, a##r, acc0);                     \
    PAIR2(X1, Y1, Z1, R1, b##x, b##y, b##z, b##r, acc1);                     \
    n = (n + 1) & (NPAIRS - 1);                                              \
    LOAD_SLOT(a, n);                                                         \
} while (0)

__global__ void __launch_bounds__(TPB, 5)
collapse_kernel(const float* __restrict__ coords,
                float* __restrict__ out,
                int nblocks, float inv_b)
{
    // copyA packs atoms (2c, 2c+1); copyB packs (2c+1, 2c+2 mod N). ~18.4 KB each.
    __shared__ float4 cpyA[2 * NPAIRS + NPAIRS / 4];
    __shared__ float4 cpyB[2 * NPAIRS + NPAIRS / 4];
    __shared__ float  wsum[TPB / 32];
    __shared__ bool   isLast;

    const int t    = threadIdx.x;
    const int bx   = blockIdx.x;        // 0..2*NSEG-1
    const int h    = bx & 1;            // row-half
    const int kseg = bx >> 1;           // k-segment
    const int b    = blockIdx.y;        // batch

    // ---- prologue: this thread loads atoms 4t..4t+3, computes r, builds copyA ----
    float ax0,ax1,ax2,ax3, ay0,ay1,ay2,ay3, az0,az1,az2,az3, ar0,ar1,ar2,ar3;
    {
        const float4* cb4 = (const float4*)(coords + (size_t)b * (3 * N_ATOMS));
        float4 f0 = cb4[3 * t + 0];
        float4 f1 = cb4[3 * t + 1];
        float4 f2 = cb4[3 * t + 2];
        ax0 = f0.x; ay0 = f0.y; az0 = f0.z;
        ax1 = f0.w; ay1 = f1.x; az1 = f1.y;
        ax2 = f1.z; ay2 = f1.w; az2 = f2.x;
        ax3 = f2.y; ay3 = f2.z; az3 = f2.w;
        ar0 = fmaf(ax0, ax0, fmaf(ay0, ay0, az0 * az0));
        ar1 = fmaf(ax1, ax1, fmaf(ay1, ay1, az1 * az1));
        ar2 = fmaf(ax2, ax2, fmaf(ay2, ay2, az2 * az2));
        ar3 = fmaf(ax3, ax3, fmaf(ay3, ay3, az3 * az3));
        cpyA[PSLOT(2 * t)    ] = make_float4(ax0, ax1, ay0, ay1);
        cpyA[PSLOT(2 * t) + 1] = make_float4(az0, az1, ar0, ar1);
        cpyA[PSLOT(2 * t + 1)    ] = make_float4(ax2, ax3, ay2, ay3);
        cpyA[PSLOT(2 * t + 1) + 1] = make_float4(az2, az3, ar2, ar3);
    }
    __syncthreads();

    // ---- build copyB (needs atom 4t+4 -> read from copyA) ----
    {
        int cn = (2 * t + 2) & (NPAIRS - 1);
        float4 n1 = cpyA[PSLOT(cn)];
        float4 n2 = cpyA[PSLOT(cn) + 1];
        float nx = n1.x, ny = n1.z, nz = n2.x, nr = n2.z;   // low half = atom 4t+4
        cpyB[PSLOT(2 * t)    ] = make_float4(ax1, ax2, ay1, ay2);
        cpyB[PSLOT(2 * t) + 1] = make_float4(az1, az2, ar1, ar2);
        cpyB[PSLOT(2 * t + 1)    ] = make_float4(ax3, nx, ay3, ny);
        cpyB[PSLOT(2 * t + 1) + 1] = make_float4(az3, nz, ar3, nr);
    }
    __syncthreads();

    // ---- row assignment: parity per WARP (conflict-free LDS phases) ----
    const int w    = t >> 5;
    const int lane = t & 31;
    const int p    = w & 1;                       // 0: even rows (copyB), 1: odd rows (copyA)
    const int m    = h * 128 + (w >> 1) * 32 + lane;   // 0..255
    const int i0   = 4 * m + p;                   // rows i0 and i0+2 (same parity)
    const float4* cp = p ? cpyA : cpyB;

    // ---- row constants from copyA ----
    u64 X0,Y0,Z0,R0, X1,Y1,Z1,R1;
    {
        #define ROWCONST(i, X, Y, Z, R) do {                                 \
            int _c = (i) >> 1;                                               \
            float4 _q1 = cpyA[PSLOT(_c)];                                    \
            float4 _q2 = cpyA[PSLOT(_c) + 1];                                \
            float _xi = p ? _q1.y : _q1.x;                                   \
            float _yi = p ? _q1.w : _q1.z;                                   \
            float _zi = p ? _q2.y : _q2.x;                                   \
            float _ri = (p ? _q2.w : _q2.z) + 1e-8f;                         \
            X = pack2(-2.f * _xi, -2.f * _xi);                               \
            Y = pack2(-2.f * _yi, -2.f * _yi);                               \
            Z = pack2(-2.f * _zi, -2.f * _zi);                               \
            R = pack2(_ri, _ri);                                             \
        } while (0)
        ROWCONST(i0,     X0, Y0, Z0, R0);
        ROWCONST(i0 + 2, X1, Y1, Z1, R1);
        #undef ROWCONST
    }

    // ---- prime 2-slot window: k0 = first odd k of this segment ----
    const int k0 = 1 + 2 * kseg * PSTEPS;
    const int c0 = ((i0 + k0) >> 1) & (NPAIRS - 1);
    u64 Ax,Ay,Az,Ar, Bx,By,Bz,Br;
    LOAD_SLOT(A, c0);
    LOAD_SLOT(B, (c0 + 1) & (NPAIRS - 1));
    int n = (c0 + 1) & (NPAIRS - 1);

    float acc0 = 0.f, acc1 = 0.f;

    // ---- main loop: PSTEPS packed k-steps, slots ping-pong ----
    #pragma unroll 4
    for (int it = 0; it < PSTEPS / 2; ++it) {
        STEP2(A, B);
        STEP2(B, A);
    }

    // ---- k=512 double-count correction (last segment only) ----
    if (kseg == NSEG - 1) {
        #pragma unroll
        for (int r = 0; r < 2; ++r) {
            int i = i0 + 2 * r;
            int ci = i >> 1;
            float4 s1 = cpyA[PSLOT(ci)];
            float4 s2 = cpyA[PSLOT(ci) + 1];
            float xi = p ? s1.y : s1.x;
            float yi = p ? s1.w : s1.z;
            float zi = p ? s2.y : s2.x;
            float ri = (p ? s2.w : s2.z) + 1e-8f;
            int j  = (i + 512) & (N_ATOMS - 1);
            int cj = j >> 1;
            float4 q1 = cpyA[PSLOT(cj)];
            float4 q2 = cpyA[PSLOT(cj) + 1];
            float xj = p ? q1.y : q1.x;
            float yj = p ? q1.w : q1.z;
            float zj = p ? q2.y : q2.x;
            float rj = p ? q2.w : q2.z;
            float dot = fmaf(xi, xj, fmaf(yi, yj, zi * zj));
            float d2  = fmaf(-2.f, dot, ri + rj);
            float v   = fmaxf(2.9f - fsqrt_approx(d2), 0.0f);
            acc0 = fmaf(v, -0.5f * v, acc0);
        }
    }

    float acc = acc0 + acc1;

    // ---- intra-CTA reduction ----
    #pragma unroll
    for (int o = 16; o > 0; o >>= 1)
        acc += __shfl_down_sync(0xFFFFFFFFu, acc, o);
    if (lane == 0) wsum[w] = acc;
    __syncthreads();

    if (t == 0) {
        float s = 0.f;
        #pragma unroll
        for (int q = 0; q < TPB / 32; ++q) s += wsum[q];
        g_partials[blockIdx.y * gridDim.x + blockIdx.x] = s;
        __threadfence();
        unsigned int c = atomicAdd(&g_count, 1u);
        isLast = (c == (unsigned int)(nblocks - 1));
    }
    __syncthreads();

    // ---- last CTA: fixed-order deterministic final reduce ----
    if (isLast) {
        __threadfence();
        if (t < 32) {
            float s = 0.f;
            for (int k = t; k < nblocks; k += 32)
                s += g_partials[k];
            #pragma unroll
            for (int o = 16; o > 0; o >>= 1)
                s += __shfl_down_sync(0xFFFFFFFFu, s, o);
            if (t == 0) {
                out[0] = s * inv_b;
                g_count = 0;   // reset for graph replay
            }
        }
    }
}

extern "C" void kernel_launch(void* const* d_in, const int* in_sizes, int n_in,
                              void* d_out, int out_size)
{
    const float* coords = (const float*)d_in[0];
    const int B = in_sizes[0] / (3 * N_ATOMS);   // 64

    // allow 5 CTAs x 37KB static smem per SM (one-time, idempotent, not a stream op)
    static bool configured = false;
    if (!configured) {
        cudaFuncSetAttribute(collapse_kernel,
                             cudaFuncAttributePreferredSharedMemoryCarveout, 100);
        configured = true;
    }

    dim3 grid(2 * NSEG, B);                       // (16, 64) = 1024 CTAs
    const int nblocks = 2 * NSEG * B;
    collapse_kernel<<<grid, TPB>>>(coords, (float*)d_out, nblocks, 1.0f / (float)B);
}

// round 7
// speedup vs baseline: 1.1082x; 1.1082x over previous
#include <cuda_runtime.h>

#define N_ATOMS 1024
#define NPAIRS  512            // packed column-pairs per copy
#define TPB     256
#define NSEG    4              // k-segments; 256 packed k-steps total
#define PSTEPS  64             // packed k-steps per CTA
#define DUPG    34             // duplicated tail groups (68 slots >= PSTEPS+4)
#define NGROUPS (NPAIRS / 2 + DUPG)   // 290 groups of 2 slots (80B each)

__device__ float g_partials[1024];
__device__ unsigned int g_count = 0;

typedef unsigned long long u64;

__device__ __forceinline__ u64 fma2(u64 a, u64 b, u64 c) {
    u64 d; asm("fma.rn.f32x2 %0, %1, %2, %3;" : "=l"(d) : "l"(a), "l"(b), "l"(c)); return d;
}
__device__ __forceinline__ u64 add2(u64 a, u64 b) {
    u64 d; asm("add.rn.f32x2 %0, %1, %2;" : "=l"(d) : "l"(a), "l"(b)); return d;
}
__device__ __forceinline__ u64 pack2(float lo, float hi) {
    u64 d; asm("mov.b64 %0, {%1, %2};" : "=l"(d) : "f"(lo), "f"(hi)); return d;
}
__device__ __forceinline__ float fsqrt_approx(float x) {
    float r; asm("sqrt.approx.f32 %0, %1;" : "=f"(r) : "f"(x)); return r;
}

// slot c lives at byte 80*(c>>1) + 32*(c&1); group g occupies float4 indices 5g..5g+4
#define SLOTBYTE(c) (80 * ((c) >> 1) + 32 * ((c) & 1))

// one packed op = 2 pairs
#define PAIR2(X, Y, Z, R, sx, sy, sz, sr, ACC) do {                          \
    u64 _t = fma2(X, sx, fma2(Y, sy, fma2(Z, sz, sr)));                      \
    u64 _d2 = add2(_t, R);                                                   \
    float _a, _b;                                                            \
    asm("mov.b64 {%0, %1}, %2;" : "=f"(_a), "=f"(_b) : "l"(_d2));            \
    float _v0 = fmaxf(2.9f - fsqrt_approx(_a), 0.0f);                        \
    float _v1 = fmaxf(2.9f - fsqrt_approx(_b), 0.0f);                        \
    ACC = fmaf(_v0, _v0, ACC);                                               \
    ACC = fmaf(_v1, _v1, ACC);                                               \
} while (0)

#define LOAD_SLOT(s, byteoff) do {                                           \
    const ulonglong2* _p = (const ulonglong2*)(cpc + (byteoff));             \
    ulonglong2 _u = _p[0];                                                   \
    ulonglong2 _w = _p[1];                                                   \
    s##x = _u.x; s##y = _u.y; s##z = _w.x; s##r = _w.y;                      \
} while (0)

// one k-step: rows use slots (a, b); refill a with next slot; 1 IADD of addressing
#define STEP(a, b, INC) do {                                                 \
    PAIR2(X0, Y0, Z0, R0, a##x, a##y, a##z, a##r, acc0);                     \
    PAIR2(X1, Y1, Z1, R1, b##x, b##y, b##z, b##r, acc1);                     \
    LOAD_SLOT(a, ldaddr);                                                    \
    ldaddr += (INC);                                                         \
} while (0)

__global__ void __launch_bounds__(TPB, 4)
collapse_kernel(const float* __restrict__ coords,
                float* __restrict__ out,
                int nblocks, float inv_b)
{
    // copyA packs atoms (2c,2c+1); copyB packs (2c+1,2c+2 mod N); dup tail, no wrap.
    __shared__ float4 cpyA[5 * NGROUPS];    // 23.2 KB
    __shared__ float4 cpyB[5 * NGROUPS];    // 23.2 KB
    __shared__ float  wsum[TPB / 32];
    __shared__ bool   isLast;

    const int t    = threadIdx.x;
    const int bx   = blockIdx.x;        // 0..2*NSEG-1
    const int h    = bx & 1;            // row-half
    const int kseg = bx >> 1;           // k-segment 0..NSEG-1
    const int b    = blockIdx.y;        // batch

    // ---- prologue: thread t loads atoms 4t..4t+3, computes r ----
    float ax0,ax1,ax2,ax3, ay0,ay1,ay2,ay3, az0,az1,az2,az3, ar0,ar1,ar2,ar3;
    {
        const float4* cb4 = (const float4*)(coords + (size_t)b * (3 * N_ATOMS));
        float4 f0 = cb4[3 * t + 0];
        float4 f1 = cb4[3 * t + 1];
        float4 f2 = cb4[3 * t + 2];
        ax0 = f0.x; ay0 = f0.y; az0 = f0.z;
        ax1 = f0.w; ay1 = f1.x; az1 = f1.y;
        ax2 = f1.z; ay2 = f1.w; az2 = f2.x;
        ax3 = f2.y; ay3 = f2.z; az3 = f2.w;
        ar0 = fmaf(ax0, ax0, fmaf(ay0, ay0, az0 * az0));
        ar1 = fmaf(ax1, ax1, fmaf(ay1, ay1, az1 * az1));
        ar2 = fmaf(ax2, ax2, fmaf(ay2, ay2, az2 * az2));
        ar3 = fmaf(ax3, ax3, fmaf(ay3, ay3, az3 * az3));
        // copyA group t (slots 2t, 2t+1)
        float4 g0 = make_float4(ax0, ax1, ay0, ay1);
        float4 g1 = make_float4(az0, az1, ar0, ar1);
        float4 g2 = make_float4(ax2, ax3, ay2, ay3);
        float4 g3 = make_float4(az2, az3, ar2, ar3);
        cpyA[5 * t + 0] = g0; cpyA[5 * t + 1] = g1;
        cpyA[5 * t + 2] = g2; cpyA[5 * t + 3] = g3;
        if (t < DUPG) {   // dup tail
            int gd = 5 * (NPAIRS / 2 + t);
            cpyA[gd + 0] = g0; cpyA[gd + 1] = g1;
            cpyA[gd + 2] = g2; cpyA[gd + 3] = g3;
        }
    }
    __syncthreads();

    // ---- build copyB (needs atom 4t+4 -> read from copyA) ----
    {
        int cn = (2 * t + 2) & (NPAIRS - 1);           // slot holding atom 4t+4 (low half)
        int gn = 5 * (cn >> 1) + 2 * (cn & 1);
        float4 n1 = cpyA[gn];
        float4 n2 = cpyA[gn + 1];
        float nx = n1.x, ny = n1.z, nz = n2.x, nr = n2.z;
        float4 g0 = make_float4(ax1, ax2, ay1, ay2);
        float4 g1 = make_float4(az1, az2, ar1, ar2);
        float4 g2 = make_float4(ax3, nx, ay3, ny);
        float4 g3 = make_float4(az3, nz, ar3, nr);
        cpyB[5 * t + 0] = g0; cpyB[5 * t + 1] = g1;
        cpyB[5 * t + 2] = g2; cpyB[5 * t + 3] = g3;
        if (t < DUPG) {
            int gd = 5 * (NPAIRS / 2 + t);
            cpyB[gd + 0] = g0; cpyB[gd + 1] = g1;
            cpyB[gd + 2] = g2; cpyB[gd + 3] = g3;
        }
    }
    __syncthreads();

    // ---- row assignment: parity per WARP (conflict-free LDS phases) ----
    const int w    = t >> 5;
    const int lane = t & 31;
    const int p    = w & 1;                            // 0: even rows (copyB), 1: odd (copyA)
    const int m    = h * 128 + (w >> 1) * 32 + lane;   // 0..255
    const int i0   = 4 * m + p;                        // rows i0 and i0+2
    const char* cpc = (const char*)(p ? cpyA : cpyB);

    // ---- row constants from copyA ----
    u64 X0,Y0,Z0,R0, X1,Y1,Z1,R1;
    {
        #define ROWCONST(i, X, Y, Z, R) do {                                 \
            int _c = (i) >> 1;                                               \
            int _g = 5 * (_c >> 1) + 2 * (_c & 1);                           \
            float4 _q1 = cpyA[_g];                                           \
            float4 _q2 = cpyA[_g + 1];                                       \
            float _xi = p ? _q1.y : _q1.x;                                   \
            float _yi = p ? _q1.w : _q1.z;                                   \
            float _zi = p ? _q2.y : _q2.x;                                   \
            float _ri = (p ? _q2.w : _q2.z) + 1e-8f;                         \
            X = pack2(-2.f * _xi, -2.f * _xi);                               \
            Y = pack2(-2.f * _yi, -2.f * _yi);                               \
            Z = pack2(-2.f * _zi, -2.f * _zi);                               \
            R = pack2(_ri, _ri);                                             \
        } while (0)
        ROWCONST(i0,     X0, Y0, Z0, R0);
        ROWCONST(i0 + 2, X1, Y1, Z1, R1);
        #undef ROWCONST
    }

    // ---- prime 4-slot window; linear walk, alternating +32/+48 increments ----
    const int k0 = 1 + 2 * kseg * PSTEPS;
    const int c0 = ((i0 + k0) >> 1) & (NPAIRS - 1);
    const int iA = (c0 & 1) ? 48 : 32;
    const int iB = 80 - iA;
    int a0 = SLOTBYTE(c0);
    int a1 = a0 + iA;
    int a2 = a1 + iB;
    int a3 = a2 + iA;
    int ldaddr = a3 + iB;                              // next slot to load (c0+4)

    u64 Ax,Ay,Az,Ar, Bx,By,Bz,Br, Cx,Cy,Cz,Cr, Dx,Dy,Dz,Dr;
    LOAD_SLOT(A, a0);
    LOAD_SLOT(B, a1);
    LOAD_SLOT(C, a2);
    LOAD_SLOT(D, a3);

    float acc0 = 0.f, acc1 = 0.f;

    // ---- main loop: 64 k-steps = 16 x 4-step rotation ----
    #pragma unroll 2
    for (int it = 0; it < PSTEPS / 4; ++it) {
        STEP(A, B, iA);
        STEP(B, C, iB);
        STEP(C, D, iA);
        STEP(D, A, iB);
    }

    // ---- k=512 double-count correction (last segment only) ----
    if (kseg == NSEG - 1) {
        #pragma unroll
        for (int r = 0; r < 2; ++r) {
            int i = i0 + 2 * r;
            int ci = i >> 1;
            int gi = 5 * (ci >> 1) + 2 * (ci & 1);
            float4 s1 = cpyA[gi];
            float4 s2 = cpyA[gi + 1];
            float xi = p ? s1.y : s1.x;
            float yi = p ? s1.w : s1.z;
            float zi = p ? s2.y : s2.x;
            float ri = (p ? s2.w : s2.z) + 1e-8f;
            int j  = (i + 512) & (N_ATOMS - 1);
            int cj = j >> 1;
            int gj = 5 * (cj >> 1) + 2 * (cj & 1);
            float4 q1 = cpyA[gj];
            float4 q2 = cpyA[gj + 1];
            float xj = p ? q1.y : q1.x;
            float yj = p ? q1.w : q1.z;
            float zj = p ? q2.y : q2.x;
            float rj = p ? q2.w : q2.z;
            float dot = fmaf(xi, xj, fmaf(yi, yj, zi * zj));
            float d2  = fmaf(-2.f, dot, ri + rj);
            float v   = fmaxf(2.9f - fsqrt_approx(d2), 0.0f);
            acc0 = fmaf(v, -0.5f * v, acc0);
        }
    }

    float acc = acc0 + acc1;

    // ---- intra-CTA reduction ----
    #pragma unroll
    for (int o = 16; o > 0; o >>= 1)
        acc += __shfl_down_sync(0xFFFFFFFFu, acc, o);
    if (lane == 0) wsum[w] = acc;
    __syncthreads();

    if (t == 0) {
        float s = 0.f;
        #pragma unroll
        for (int q = 0; q < TPB / 32; ++q) s += wsum[q];
        g_partials[blockIdx.y * gridDim.x + blockIdx.x] = s;
        __threadfence();
        unsigned int c = atomicAdd(&g_count, 1u);
        isLast = (c == (unsigned int)(nblocks - 1));
    }
    __syncthreads();

    // ---- last CTA: fixed-order deterministic final reduce ----
    if (isLast) {
        __threadfence();
        if (t < 32) {
            float s = 0.f;
            for (int k = t; k < nblocks; k += 32)
                s += g_partials[k];
            #pragma unroll
            for (int o = 16; o > 0; o >>= 1)
                s += __shfl_down_sync(0xFFFFFFFFu, s, o);
            if (t == 0) {
                out[0] = s * inv_b;
                g_count = 0;   // reset for graph replay
            }
        }
    }
}

extern "C" void kernel_launch(void* const* d_in, const int* in_sizes, int n_in,
                              void* d_out, int out_size)
{
    const float* coords = (const float*)d_in[0];
    const int B = in_sizes[0] / (3 * N_ATOMS);   // 64

    static bool configured = false;
    if (!configured) {
        cudaFuncSetAttribute(collapse_kernel,
                             cudaFuncAttributePreferredSharedMemoryCarveout, 100);
        configured = true;
    }

    dim3 grid(2 * NSEG, B);                      // (8, 64) = 512 CTAs, single wave
    const int nblocks = 2 * NSEG * B;
    collapse_kernel<<<grid, TPB>>>(coords, (float*)d_out, nblocks, 1.0f / (float)B);
}